// round 11
// baseline (speedup 1.0000x reference)
#include <cuda_runtime.h>
#include <cstdint>

#define H    768
#define H4   192
#define NT   192            // threads per block (one per float4 column)
#define NB   740            // 148 SMs x 5 blocks, all co-resident by construction
#define RPC  4              // rows per streamed chunk
#define CHB  (RPC * H * 4)  // 12288 bytes per chunk
#define NSTG 3              // pipeline stages
#define NINFU 0xff800000u

// ---------------- scratch (__device__ globals: allocation-free) ----------------
__device__ __align__(16) float g_colmax[H];
__device__ __align__(16) float g_qw[H];
__device__ __align__(16) float g_v[H];
__device__ __align__(16) float g_ep[H];
__device__ float g_pm[NB], g_ps[NB];
__device__ __align__(16) float g_pacc[NB * H];
__device__ unsigned g_cnt = 0, g_gen = 0;
__device__ unsigned g_ctr[4];                 // work-steal counters (3 used)

// ---------------- helpers ----------------
__device__ __forceinline__ void atomicMaxFloat(float* addr, float val) {
    if (val >= 0.0f) atomicMax((int*)addr, __float_as_int(val));
    else             atomicMin((unsigned int*)addr, __float_as_uint(val));
}
__device__ __forceinline__ float warpReduceSum(float v) {
    #pragma unroll
    for (int o = 16; o; o >>= 1) v += __shfl_xor_sync(0xffffffffu, v, o);
    return v;
}
__device__ __forceinline__ float warpReduceMax(float v) {
    #pragma unroll
    for (int o = 16; o; o >>= 1) v = fmaxf(v, __shfl_xor_sync(0xffffffffu, v, o));
    return v;
}
// thread t copies ITS OWN 4 columns (16 B) of each of the RPC rows of chunk c
__device__ __forceinline__ void issue_own4(uint32_t sb0, int stage, const float4* src,
                                           int c, int t) {
    uint32_t d = sb0 + (uint32_t)(stage * CHB + t * 16);
    const float4* s = src + (size_t)c * (RPC * H4) + t;
    #pragma unroll
    for (int g = 0; g < RPC; g++)
        asm volatile("cp.async.cg.shared.global [%0], [%1], 16;"
                     :: "r"(d + (uint32_t)(g * H4 * 16)), "l"(s + g * H4));
}
#define CPA_COMMIT() asm volatile("cp.async.commit_group;" ::: "memory")
#define CPA_WAIT()   asm volatile("cp.async.wait_group 2;" ::: "memory")  // NSTG-1

// grid barrier: arrival atomics, POLL VIA PLAIN VOLATILE LOADS (no atomic contention)
__device__ __forceinline__ void gsync() {
    __syncthreads();
    if (threadIdx.x == 0) {
        __threadfence();
        volatile unsigned* vg = &g_gen;
        unsigned gen = *vg;
        if (atomicAdd(&g_cnt, 1u) == NB - 1u) {
            atomicExch(&g_cnt, 0u);
            __threadfence();
            atomicAdd(&g_gen, 1u);
        } else {
            while (*vg == gen) __nanosleep(128);
            __threadfence();
        }
    }
    __syncthreads();
}

// ---------------- the single persistent kernel ----------------
__global__ void __launch_bounds__(NT, 5)
mega_kernel(const float4* __restrict__ fact4, const float4* __restrict__ ep4,
            const float* __restrict__ W, float* __restrict__ out, int N, int M) {
    int b = blockIdx.x, t = threadIdx.x;
    int lane = t & 31, wid = t >> 5;
    float ninf = __uint_as_float(NINFU);

    __shared__ __align__(16) float4 s_buf[NSTG][RPC * H4];   // 36 KB stream stages
    __shared__ float s_sp[RPC][NT];                          // 3 KB dot partials
    __shared__ float s_sd[RPC];
    __shared__ float s_red[8];
    __shared__ int s_cq[NSTG];
    __shared__ int s_cn2[2];           // parity-buffered next-chunk broadcast
    __shared__ unsigned s_ni2[2];      // parity-buffered issued-count broadcast
    __shared__ unsigned s_ni0;

    uint32_t sb0 = (uint32_t)__cvta_generic_to_shared(&s_buf[0][0]);

    // ---- P0: init ----
    if (b == 0) {
        for (int i = t; i < H; i += NT) {
            g_colmax[i] = ninf; g_qw[i] = 0.0f; g_ep[i] = 0.0f;
            out[i] = 0.0f; out[i + H] = 0.0f;
        }
        if (t < 4) g_ctr[t] = 0u;
    }
    gsync();   // B1

    // prefill macro: t0 grabs up to NSTG chunks, all threads issue their columns
    #define PREFILL(CTRX, SRC, NCH)                                              \
        unsigned done = 0, niss; int cons = 0, iss = 0;                          \
        if (t == 0) { unsigned k = 0;                                            \
            for (int i = 0; i < NSTG; i++) {                                     \
                unsigned c = atomicAdd(&(CTRX), 1u);                             \
                if (c < (unsigned)(NCH)) { s_cq[i] = (int)c; k++; }              \
                else s_cq[i] = -1; }                                             \
            s_ni0 = k; }                                                         \
        __syncthreads();                                                         \
        for (int i = 0; i < NSTG; i++) { int c = s_cq[i];                        \
            if (c >= 0) issue_own4(sb0, i, (SRC), c, t);                         \
            CPA_COMMIT(); }                                                      \
        niss = s_ni0;

    // ---- P1: column max over fact (work-stealing cp.async pipeline) ----
    {
        int nch = N / RPC;
        PREFILL(g_ctr[0], fact4, nch)
        float4 m4 = make_float4(ninf, ninf, ninf, ninf);
        while (done < niss) {
            int p = (int)(done & 1u);
            CPA_WAIT();                      // own copies of oldest stage done
            float4 x0 = s_buf[cons][0 * H4 + t];
            float4 x1 = s_buf[cons][1 * H4 + t];
            float4 x2 = s_buf[cons][2 * H4 + t];
            float4 x3 = s_buf[cons][3 * H4 + t];
            m4.x = fmaxf(m4.x, fmaxf(fmaxf(x0.x, x1.x), fmaxf(x2.x, x3.x)));
            m4.y = fmaxf(m4.y, fmaxf(fmaxf(x0.y, x1.y), fmaxf(x2.y, x3.y)));
            m4.z = fmaxf(m4.z, fmaxf(fmaxf(x0.z, x1.z), fmaxf(x2.z, x3.z)));
            m4.w = fmaxf(m4.w, fmaxf(fmaxf(x0.w, x1.w), fmaxf(x2.w, x3.w)));
            if (t == 0) {
                unsigned c = atomicAdd(&g_ctr[0], 1u);
                if (c < (unsigned)nch) { s_cn2[p] = (int)c; s_ni2[p] = niss + 1; }
                else                   { s_cn2[p] = -1;     s_ni2[p] = niss;     }
            }
            __syncthreads();
            int cn = s_cn2[p]; niss = s_ni2[p];
            if (cn >= 0) issue_own4(sb0, iss, fact4, cn, t);
            CPA_COMMIT();
            done++;
            cons = (cons + 1 == NSTG) ? 0 : cons + 1;
            iss  = (iss  + 1 == NSTG) ? 0 : iss  + 1;
        }
        int col = t * 4;
        atomicMaxFloat(&g_colmax[col + 0], m4.x);
        atomicMaxFloat(&g_colmax[col + 1], m4.y);
        atomicMaxFloat(&g_colmax[col + 2], m4.z);
        atomicMaxFloat(&g_colmax[col + 3], m4.w);
    }
    gsync();   // B2

    // ---- P2: qw[j] = sum_h colmax[h] * W[h,j]  (96 blocks) ----
    if (b < 96) {
        int j = (b & 3) * NT + t, h0 = (b >> 2) * 32;
        float a = 0.0f;
        #pragma unroll 8
        for (int i = 0; i < 32; i++)
            a += g_colmax[h0 + i] * W[(size_t)(h0 + i) * H + j];
        atomicAdd(&g_qw[j], a);
    }
    gsync();   // B3

    // fused streaming pass: work stealing + per-thread column ownership
    #define FUSED_STREAM(CTRX, SRC, NCH, VSRC)                                   \
    {                                                                            \
        int nch = (NCH);                                                         \
        PREFILL(CTRX, SRC, nch)                                                  \
        float4 vc = ((const float4*)(VSRC))[t];                                  \
        float m = ninf, s = 0.0f;                                                \
        float4 acc = make_float4(0.f, 0.f, 0.f, 0.f);                            \
        while (done < niss) {                                                    \
            int p = (int)(done & 1u);                                            \
            CPA_WAIT();                                                          \
            float4 x0 = s_buf[cons][0 * H4 + t];                                 \
            float4 x1 = s_buf[cons][1 * H4 + t];                                 \
            float4 x2 = s_buf[cons][2 * H4 + t];                                 \
            float4 x3 = s_buf[cons][3 * H4 + t];                                 \
            s_sp[0][t] = x0.x * vc.x + x0.y * vc.y + x0.z * vc.z + x0.w * vc.w;  \
            s_sp[1][t] = x1.x * vc.x + x1.y * vc.y + x1.z * vc.z + x1.w * vc.w;  \
            s_sp[2][t] = x2.x * vc.x + x2.y * vc.y + x2.z * vc.z + x2.w * vc.w;  \
            s_sp[3][t] = x3.x * vc.x + x3.y * vc.y + x3.z * vc.z + x3.w * vc.w;  \
            if (t == 0) {                                                        \
                unsigned c = atomicAdd(&(CTRX), 1u);                             \
                if (c < (unsigned)nch) { s_cn2[p] = (int)c; s_ni2[p] = niss + 1; } \
                else                   { s_cn2[p] = -1;     s_ni2[p] = niss;     } \
            }                                                                    \
            __syncthreads();   /* sp ready; cn/ni visible */                     \
            int cn = s_cn2[p]; niss = s_ni2[p];                                  \
            if (cn >= 0) issue_own4(sb0, iss, (SRC), cn, t);                     \
            CPA_COMMIT();                                                        \
            if (wid < RPC) {                                                     \
                float v = 0.0f;                                                  \
                _Pragma("unroll")                                                \
                for (int k2 = 0; k2 < 6; k2++) v += s_sp[wid][lane + 32 * k2];   \
                v = warpReduceSum(v);                                            \
                if (lane == 0) s_sd[wid] = v;                                    \
            }                                                                    \
            __syncthreads();   /* sd ready */                                    \
            float d0 = s_sd[0], d1 = s_sd[1], d2 = s_sd[2], d3 = s_sd[3];        \
            float mn = fmaxf(fmaxf(fmaxf(d0, d1), fmaxf(d2, d3)), m);            \
            float sc = __expf(m - mn);                                           \
            float w0 = __expf(d0 - mn), w1 = __expf(d1 - mn);                    \
            float w2 = __expf(d2 - mn), w3 = __expf(d3 - mn);                    \
            s = s * sc + w0 + w1 + w2 + w3;                                      \
            m = mn;                                                              \
            acc.x = acc.x * sc + w0 * x0.x + w1 * x1.x + w2 * x2.x + w3 * x3.x;  \
            acc.y = acc.y * sc + w0 * x0.y + w1 * x1.y + w2 * x2.y + w3 * x3.y;  \
            acc.z = acc.z * sc + w0 * x0.z + w1 * x1.z + w2 * x2.z + w3 * x3.z;  \
            acc.w = acc.w * sc + w0 * x0.w + w1 * x1.w + w2 * x2.w + w3 * x3.w;  \
            done++;                                                              \
            cons = (cons + 1 == NSTG) ? 0 : cons + 1;                            \
            iss  = (iss  + 1 == NSTG) ? 0 : iss  + 1;                            \
        }                                                                        \
        if (t == 0) { g_pm[b] = m; g_ps[b] = s; }                                \
        ((float4*)g_pacc)[b * H4 + t] = acc;                                     \
    }

    // ---- P3: elements_p fused pass ----
    FUSED_STREAM(g_ctr[1], ep4, M / RPC, g_qw)
    gsync();   // B4

    // merge: ALL NB blocks; each handles 4 partials x 192 columns; M,S redundant
    #define MERGE_PHASE(DST, DST2)                                               \
    {                                                                            \
        float lm = ninf;                                                         \
        _Pragma("unroll")                                                        \
        for (int q = 0; q < 4; q++) {                                            \
            int i = t + q * NT;                                                  \
            if (i < NB) lm = fmaxf(lm, g_pm[i]);                                 \
        }                                                                        \
        lm = warpReduceMax(lm);                                                  \
        if (lane == 0) s_red[wid] = lm;                                          \
        __syncthreads();                                                         \
        if (t == 0) {                                                            \
            float Mx = s_red[0];                                                 \
            _Pragma("unroll")                                                    \
            for (int i = 1; i < 6; i++) Mx = fmaxf(Mx, s_red[i]);                \
            s_red[6] = Mx;                                                       \
        }                                                                        \
        __syncthreads();                                                         \
        float Mx = s_red[6];                                                     \
        float lsum = 0.0f;                                                       \
        _Pragma("unroll")                                                        \
        for (int q = 0; q < 4; q++) {                                            \
            int i = t + q * NT;                                                  \
            if (i < NB) lsum += __expf(g_pm[i] - Mx) * g_ps[i];                  \
        }                                                                        \
        lsum = warpReduceSum(lsum);                                              \
        if (lane == 0) s_red[wid] = lsum;                                        \
        __syncthreads();                                                         \
        if (t == 0) {                                                            \
            float S = 0.0f;                                                      \
            _Pragma("unroll")                                                    \
            for (int i = 0; i < 6; i++) S += s_red[i];                           \
            s_red[7] = S;                                                        \
        }                                                                        \
        __syncthreads();                                                         \
        float S = s_red[7];                                                      \
        int w0i = (b >> 2) * 4;                                                  \
        int h = (b & 3) * NT + t;                                                \
        float a = 0.0f;                                                          \
        _Pragma("unroll")                                                        \
        for (int i = 0; i < 4; i++)                                              \
            a += __expf(g_pm[w0i + i] - Mx) * g_pacc[(size_t)(w0i + i) * H + h]; \
        a /= S;                                                                  \
        atomicAdd(&(DST)[h], a);                                                 \
        if (DST2) atomicAdd(&((float*)(DST2))[h], a);                            \
        __syncthreads();                                                         \
    }

    // ---- P4: merge ep partials -> g_ep and out[768:] ----
    MERGE_PHASE(g_ep, out + H)
    gsync();   // B5

    // ---- P5: v[row] = W[row,:] . ep_  (128 blocks x 6 warps) ----
    if (b < 128) {
        int row = b * 6 + wid;
        const float4* r = (const float4*)(W + (size_t)row * H);
        float pdot = 0.0f;
        #pragma unroll
        for (int k = 0; k < 6; k++) {
            float4 a4 = r[lane + 32 * k];
            float4 e4 = ((const float4*)g_ep)[lane + 32 * k];
            pdot += a4.x * e4.x + a4.y * e4.y + a4.z * e4.z + a4.w * e4.w;
        }
        pdot = warpReduceSum(pdot);
        if (lane == 0) g_v[row] = pdot;
    }
    gsync();   // B6

    // ---- P6: fact fused pass (L2-warm from P1 via .cg allocation) ----
    FUSED_STREAM(g_ctr[2], fact4, N / RPC, g_v)
    gsync();   // B7

    // ---- P7: merge fact partials -> out[0:768] ----
    MERGE_PHASE(out, (float*)nullptr)
}

// ---------------- launch ----------------
extern "C" void kernel_launch(void* const* d_in, const int* in_sizes, int n_in,
                              void* d_out, int out_size) {
    const float *fact = nullptr, *ep = nullptr, *W = nullptr;
    int N = 0, M = 0;
    for (int i = 0; i < n_in; i++) {
        long long sz = in_sizes[i];
        if (sz == (long long)H * H)           W    = (const float*)d_in[i];
        else if (sz == (long long)4096 * H) { ep   = (const float*)d_in[i]; M = 4096; }
        else                                { fact = (const float*)d_in[i]; N = (int)(sz / H); }
    }
    mega_kernel<<<NB, NT>>>((const float4*)fact, (const float4*)ep, W,
                            (float*)d_out, N, M);
}

// round 16
// speedup vs baseline: 1.0712x; 1.0712x over previous
#include <cuda_runtime.h>
#include <cstdint>

#define H     768
#define H4    192
#define NT    192            // 6 warps per block
#define NBMAX 1184
#define NINFU 0xff800000u

// ---------------- scratch (__device__ globals: allocation-free) ----------------
__device__ __align__(16) float g_colmax[H];
__device__ __align__(16) float g_qw[H];
__device__ __align__(16) float g_v[H];
__device__ __align__(16) float g_ep[H];
__device__ float g_pm[NBMAX], g_ps[NBMAX];
__device__ __align__(16) float g_pacc[(size_t)NBMAX * H];
__device__ unsigned g_cnt = 0, g_gen = 0;

// ---------------- helpers ----------------
__device__ __forceinline__ void atomicMaxFloat(float* addr, float val) {
    if (val >= 0.0f) atomicMax((int*)addr, __float_as_int(val));
    else             atomicMin((unsigned int*)addr, __float_as_uint(val));
}
__device__ __forceinline__ float warpReduceSum(float v) {
    #pragma unroll
    for (int o = 16; o; o >>= 1) v += __shfl_xor_sync(0xffffffffu, v, o);
    return v;
}
__device__ __forceinline__ float warpReduceMax(float v) {
    #pragma unroll
    for (int o = 16; o; o >>= 1) v = fmaxf(v, __shfl_xor_sync(0xffffffffu, v, o));
    return v;
}
// lane copies ITS OWN 6 float4 columns of one row into the warp's private slot
__device__ __forceinline__ void issue_row(uint32_t dstb, const float4* src, int lane) {
    #pragma unroll
    for (int k = 0; k < 6; k++)
        asm volatile("cp.async.cg.shared.global [%0], [%1], 16;"
                     :: "r"(dstb + (uint32_t)((lane + 32 * k) * 16)),
                        "l"(src + lane + 32 * k));
    asm volatile("cp.async.commit_group;" ::: "memory");
}
__device__ __forceinline__ void cpa_empty() { asm volatile("cp.async.commit_group;" ::: "memory"); }
__device__ __forceinline__ void cpa_wait1() { asm volatile("cp.async.wait_group 1;" ::: "memory"); }
__device__ __forceinline__ void cpa_wait0() { asm volatile("cp.async.wait_group 0;" ::: "memory"); }

// grid barrier: arrival atomics; poll via plain volatile loads
__device__ __forceinline__ void gsync() {
    __syncthreads();
    if (threadIdx.x == 0) {
        __threadfence();
        volatile unsigned* vg = &g_gen;
        unsigned gen = *vg;
        if (atomicAdd(&g_cnt, 1u) == gridDim.x - 1u) {
            atomicExch(&g_cnt, 0u);
            __threadfence();
            atomicAdd(&g_gen, 1u);
        } else {
            while (*vg == gen) __nanosleep(128);
            __threadfence();
        }
    }
    __syncthreads();
}

__device__ __forceinline__ void f4max(float4& m, const float4& x) {
    m.x = fmaxf(m.x, x.x); m.y = fmaxf(m.y, x.y);
    m.z = fmaxf(m.z, x.z); m.w = fmaxf(m.w, x.w);
}
__device__ __forceinline__ void f4axpy(float4& a, float w, const float4& x) {
    a.x += w * x.x; a.y += w * x.y; a.z += w * x.z; a.w += w * x.w;
}
__device__ __forceinline__ void f4scaladd(float4& a, float sc, const float4& x) {
    a.x = a.x * sc + x.x; a.y = a.y * sc + x.y;
    a.z = a.z * sc + x.z; a.w = a.w * sc + x.w;
}

// Warp-autonomous fused pass: dot + epoch online softmax + register acc.
// No block barriers in the loop; per-lane cp.async wait only.
__device__ __forceinline__ void fused_pass(
    const float4* __restrict__ src, int rows, const float* __restrict__ vecsrc,
    float4 (*s_slab)[H4], float4* s_vec, float* s_m, float* s_s,
    uint32_t slotA, uint32_t slotB,
    int b, int t, int lane, int wid, int gw, int NW, float ninf)
{
    if (t < H4) s_vec[t] = ((const float4*)vecsrc)[t];
    __syncthreads();

    float4 acc[6];
    #pragma unroll
    for (int k = 0; k < 6; k++) acc[k] = make_float4(0.f, 0.f, 0.f, 0.f);
    float m0 = ninf, s = 0.0f;

    int r = gw;
    if (r < rows) {
        issue_row(slotA, src + (size_t)r * H4, lane);
        if (r + NW < rows) issue_row(slotB, src + (size_t)(r + NW) * H4, lane);
        else               cpa_empty();
        int slot = 0, first = 1;
        for (; r < rows; r += NW, slot ^= 1) {
            cpa_wait1();                       // this lane's oldest row copy done
            const float4* S = &s_slab[wid * 2 + slot][0];
            float4 x[6];
            float p = 0.0f;
            #pragma unroll
            for (int k = 0; k < 6; k++) {
                x[k] = S[lane + 32 * k];
                float4 vc = s_vec[lane + 32 * k];
                p += x[k].x * vc.x + x[k].y * vc.y + x[k].z * vc.z + x[k].w * vc.w;
            }
            float d = warpReduceSum(p);
            if (r + 2 * NW < rows)
                issue_row(slot ? slotB : slotA, src + (size_t)(r + 2 * NW) * H4, lane);
            else cpa_empty();

            if (first) {
                first = 0; m0 = d; s = 1.0f;
                #pragma unroll
                for (int k = 0; k < 6; k++) acc[k] = x[k];
            } else if (d > m0 + 30.0f) {       // rare epoch rescale
                float sc = __expf(m0 - d);
                s = s * sc + 1.0f;
                #pragma unroll
                for (int k = 0; k < 6; k++) f4scaladd(acc[k], sc, x[k]);
                m0 = d;
            } else {
                float w = __expf(d - m0);
                s += w;
                #pragma unroll
                for (int k = 0; k < 6; k++) f4axpy(acc[k], w, x[k]);
            }
        }
    }
    cpa_wait0();
    __syncthreads();                  // all warps done consuming slabs
    float4* cmb = &s_slab[0][0];      // reuse slab: [6 warps][192 cols]
    #pragma unroll
    for (int k = 0; k < 6; k++) cmb[wid * H4 + lane + 32 * k] = acc[k];
    if (lane == 0) { s_m[wid] = m0; s_s[wid] = s; }
    __syncthreads();

    float mb = s_m[0];
    #pragma unroll
    for (int w = 1; w < 6; w++) mb = fmaxf(mb, s_m[w]);
    float4 a4 = make_float4(0.f, 0.f, 0.f, 0.f);
    float sb = 0.0f;
    if (mb != ninf) {
        #pragma unroll
        for (int w = 0; w < 6; w++) {
            float e = __expf(s_m[w] - mb);
            sb += e * s_s[w];
            float4 c = cmb[w * H4 + t];
            f4axpy(a4, e, c);
        }
    }
    ((float4*)g_pacc)[(size_t)b * H4 + t] = a4;
    if (t == 0) { g_pm[b] = mb; g_ps[b] = sb; }
    __syncthreads();
}

// merge: each block = (partial-group b>>2 of 4, column-slice b&3 of 192)
__device__ __forceinline__ void merge_phase(
    float* dst, float* dst2, float* s_red,
    int NBv, int b, int t, int lane, int wid, float ninf)
{
    float lm = ninf;
    for (int i = t; i < NBv; i += NT) lm = fmaxf(lm, g_pm[i]);
    lm = warpReduceMax(lm);
    if (lane == 0) s_red[wid] = lm;
    __syncthreads();
    if (t == 0) {
        float Mx = s_red[0];
        #pragma unroll
        for (int i = 1; i < 6; i++) Mx = fmaxf(Mx, s_red[i]);
        s_red[6] = Mx;
    }
    __syncthreads();
    float Mx = s_red[6];
    float ls = 0.0f;
    for (int i = t; i < NBv; i += NT) ls += __expf(g_pm[i] - Mx) * g_ps[i];
    ls = warpReduceSum(ls);
    if (lane == 0) s_red[wid] = ls;
    __syncthreads();
    if (t == 0) {
        float S = 0.0f;
        #pragma unroll
        for (int i = 0; i < 6; i++) S += s_red[i];
        s_red[7] = S;
    }
    __syncthreads();
    float S = s_red[7];

    int w0i = (b >> 2) * 4;
    int h = (b & 3) * NT + t;
    float a = 0.0f;
    #pragma unroll
    for (int i = 0; i < 4; i++)
        a += __expf(g_pm[w0i + i] - Mx) * g_pacc[(size_t)(w0i + i) * H + h];
    a /= S;
    atomicAdd(&dst[h], a);
    if (dst2) atomicAdd(&dst2[h], a);
    __syncthreads();
}

// ---------------- the single persistent kernel ----------------
__global__ void __launch_bounds__(NT, 4)
mega_kernel(const float4* __restrict__ fact4, const float4* __restrict__ ep4,
            const float* __restrict__ W, float* __restrict__ out, int N, int M) {
    int b = blockIdx.x, t = threadIdx.x;
    int lane = t & 31, wid = t >> 5;
    float ninf = __uint_as_float(NINFU);
    const int NBv = gridDim.x;
    const int NW  = NBv * 6;           // total warps
    const int gw  = b * 6 + wid;       // global warp id

    __shared__ __align__(16) float4 s_slab[12][H4];   // 36 KB: 6 warps x 2 stages
    __shared__ __align__(16) float4 s_vec[H4];        // 3 KB projection vector
    __shared__ float s_m[6], s_s[6];
    __shared__ float s_red[8];

    uint32_t slab0 = (uint32_t)__cvta_generic_to_shared(&s_slab[0][0]);
    uint32_t slotA = slab0 + (uint32_t)(wid * 2) * 3072u;
    uint32_t slotB = slotA + 3072u;

    // ---- P0: init ----
    if (b == 0) {
        for (int i = t; i < H; i += NT) {
            g_colmax[i] = ninf; g_qw[i] = 0.0f; g_ep[i] = 0.0f;
            out[i] = 0.0f; out[i + H] = 0.0f;
        }
    }
    gsync();   // B1

    // ---- P1: column max over fact; warp-autonomous 2-stage cp.async streams ----
    {
        float4 mm[6];
        #pragma unroll
        for (int k = 0; k < 6; k++) mm[k] = make_float4(ninf, ninf, ninf, ninf);
        int r = gw;
        if (r < N) {
            issue_row(slotA, fact4 + (size_t)r * H4, lane);
            if (r + NW < N) issue_row(slotB, fact4 + (size_t)(r + NW) * H4, lane);
            else            cpa_empty();
            int slot = 0;
            for (; r < N; r += NW, slot ^= 1) {
                cpa_wait1();           // this lane's oldest row copy done
                const float4* S = &s_slab[wid * 2 + slot][0];
                #pragma unroll
                for (int k = 0; k < 6; k++) {
                    float4 x = S[lane + 32 * k];
                    f4max(mm[k], x);
                }
                if (r + 2 * NW < N)
                    issue_row(slot ? slotB : slotA, fact4 + (size_t)(r + 2 * NW) * H4, lane);
                else cpa_empty();
            }
        }
        cpa_wait0();                   // clean slate for next phase
        __syncthreads();               // all warps done consuming slabs
        float4* cmb = &s_slab[0][0];   // reuse slab: [6 warps][192 cols]
        #pragma unroll
        for (int k = 0; k < 6; k++) cmb[wid * H4 + lane + 32 * k] = mm[k];
        __syncthreads();
        float4 m4 = cmb[t];
        #pragma unroll
        for (int w = 1; w < 6; w++) { float4 x = cmb[w * H4 + t]; f4max(m4, x); }
        int col = t * 4;
        atomicMaxFloat(&g_colmax[col + 0], m4.x);
        atomicMaxFloat(&g_colmax[col + 1], m4.y);
        atomicMaxFloat(&g_colmax[col + 2], m4.z);
        atomicMaxFloat(&g_colmax[col + 3], m4.w);
    }
    gsync();   // B2

    // ---- P2: qw[j] = sum_h colmax[h] * W[h,j]  (96 blocks) ----
    if (b < 96) {
        int j = (b & 3) * NT + t, h0 = (b >> 2) * 32;
        float a = 0.0f;
        #pragma unroll 8
        for (int i = 0; i < 32; i++)
            a += g_colmax[h0 + i] * W[(size_t)(h0 + i) * H + j];
        atomicAdd(&g_qw[j], a);
    }
    gsync();   // B3

    // ---- P3: elements_p fused pass (vec = g_qw) ----
    fused_pass(ep4, M, g_qw, s_slab, s_vec, s_m, s_s, slotA, slotB,
               b, t, lane, wid, gw, NW, ninf);
    gsync();   // B4

    // ---- P4: merge ep partials -> g_ep and out[768:] ----
    merge_phase(g_ep, out + H, s_red, NBv, b, t, lane, wid, ninf);
    gsync();   // B5

    // ---- P5: v[row] = W[row,:] . ep_  (128 blocks x 6 warps) ----
    if (b < 128) {
        int row = b * 6 + wid;
        const float4* rw = (const float4*)(W + (size_t)row * H);
        float p = 0.0f;
        #pragma unroll
        for (int k = 0; k < 6; k++) {
            float4 a4 = rw[lane + 32 * k];
            float4 e4 = ((const float4*)g_ep)[lane + 32 * k];
            p += a4.x * e4.x + a4.y * e4.y + a4.z * e4.z + a4.w * e4.w;
        }
        p = warpReduceSum(p);
        if (lane == 0) g_v[row] = p;
    }
    gsync();   // B6

    // ---- P6: fact fused pass (vec = g_v) ----
    fused_pass(fact4, N, g_v, s_slab, s_vec, s_m, s_s, slotA, slotB,
               b, t, lane, wid, gw, NW, ninf);
    gsync();   // B7

    // ---- P7: merge fact partials -> out[0:768] ----
    merge_phase(out, nullptr, s_red, NBv, b, t, lane, wid, ninf);
}

// ---------------- launch ----------------
extern "C" void kernel_launch(void* const* d_in, const int* in_sizes, int n_in,
                              void* d_out, int out_size) {
    const float *fact = nullptr, *ep = nullptr, *W = nullptr;
    int N = 0, M = 0;
    for (int i = 0; i < n_in; i++) {
        long long sz = in_sizes[i];
        if (sz == (long long)H * H)           W    = (const float*)d_in[i];
        else if (sz == (long long)4096 * H) { ep   = (const float*)d_in[i]; M = 4096; }
        else                                { fact = (const float*)d_in[i]; N = (int)(sz / H); }
    }
    // deadlock-proof grid: exactly the co-residency the HW guarantees
    int bpm = 0, sms = 0, dev = 0;
    cudaGetDevice(&dev);
    cudaDeviceGetAttribute(&sms, cudaDevAttrMultiProcessorCount, dev);
    cudaOccupancyMaxActiveBlocksPerMultiprocessor(&bpm, mega_kernel, NT, 0);
    if (bpm < 1) bpm = 1;
    int nb = bpm * sms;
    if (nb > NBMAX) nb = NBMAX;
    nb &= ~3;                      // merge mapping needs NB % 4 == 0
    if (nb < 128) nb = 128;        // P5 needs >=128 blocks
    mega_kernel<<<nb, NT>>>((const float4*)fact, (const float4*)ep, W,
                            (float*)d_out, N, M);
}